// round 2
// baseline (speedup 1.0000x reference)
#include <cuda_runtime.h>
#include <math.h>

// ---------------- problem constants ----------------
#define CB   8
#define CT   24
#define CW   48
#define CD   512
#define CH   8
#define CE   64
#define CDI  1024
#define CS   64
#define CR   32
#define CKC  4
#define CDFF 2048
#define CL   1152          // T*W
#define CM   9216          // B*L

// ---------------- scratch (device globals; no cudaMalloc allowed) ----------------
__device__ float g_q[CM * CD];
__device__ float g_k[CM * CD];
__device__ float g_v[CM * CD];
__device__ float g_scores[(size_t)CB * CH * CL * CL];   // 340 MB, reused as probs
__device__ float g_attn[CM * CD];
__device__ float g_xattn[CM * CD];
__device__ float g_xz[CM * 2 * CDI];
__device__ float g_uact[CM * CDI];
__device__ float g_xdbc[CM * (CR + 2 * CS)];
__device__ float g_delta[CM * CDI];
__device__ float g_yss[CM * CDI];
__device__ float g_mamba[CM * CD];
__device__ float g_h[CM * CD];
__device__ float g_hn[CM * CD];
__device__ float g_ff1[CM * CDFF];

// ---------------- reductions ----------------
__device__ __forceinline__ float warpSum(float v) {
    #pragma unroll
    for (int o = 16; o; o >>= 1) v += __shfl_xor_sync(0xffffffffu, v, o);
    return v;
}
__device__ __forceinline__ float warpMax(float v) {
    #pragma unroll
    for (int o = 16; o; o >>= 1) v = fmaxf(v, __shfl_xor_sync(0xffffffffu, v, o));
    return v;
}
__device__ float blockSum(float v) {
    __shared__ float sh[32];
    int lane = threadIdx.x & 31, wid = threadIdx.x >> 5;
    v = warpSum(v);
    if (lane == 0) sh[wid] = v;
    __syncthreads();
    int nw = blockDim.x >> 5;
    v = (threadIdx.x < nw) ? sh[threadIdx.x] : 0.f;
    if (wid == 0) v = warpSum(v);
    if (threadIdx.x == 0) sh[0] = v;
    __syncthreads();
    float r = sh[0];
    __syncthreads();
    return r;
}
__device__ float blockMax(float v) {
    __shared__ float sh[32];
    int lane = threadIdx.x & 31, wid = threadIdx.x >> 5;
    v = warpMax(v);
    if (lane == 0) sh[wid] = v;
    __syncthreads();
    int nw = blockDim.x >> 5;
    v = (threadIdx.x < nw) ? sh[threadIdx.x] : -INFINITY;
    if (wid == 0) v = warpMax(v);
    if (threadIdx.x == 0) sh[0] = v;
    __syncthreads();
    float r = sh[0];
    __syncthreads();
    return r;
}

// ---------------- SGEMM: C = epi(A * op(B) + bias) + resid ----------------
// TB=1: C[m,n] = sum_k A[m,k]*B[n,k]   (torch Linear, both K-contiguous)
// TB=0: C[m,n] = sum_k A[m,k]*B[k,n]   (NN, for probs @ V)
// Batched via blockIdx.z: off = (z/zdiv)*s1 + (z%zdiv)*s2 per operand.
// EPI: 0 none, 1 exact GELU, 2 softplus
template <int TB, int EPI>
__global__ void sgemm_kernel(const float* __restrict__ A, const float* __restrict__ Bm,
                             const float* __restrict__ bias, const float* __restrict__ resid,
                             float* __restrict__ C,
                             int M, int N, int K, int lda, int ldb, int ldc,
                             int zdiv, long long sA1, long long sA2,
                             long long sB1, long long sB2,
                             long long sC1, long long sC2) {
    __shared__ float As[16][64];
    __shared__ float Bs[16][64];
    int z = blockIdx.z;
    int zq = z / zdiv, zr = z - zq * zdiv;
    A += zq * sA1 + (long long)zr * sA2;
    Bm += zq * sB1 + (long long)zr * sB2;
    C += zq * sC1 + (long long)zr * sC2;
    if (resid) resid += zq * sC1 + (long long)zr * sC2;

    int m0 = blockIdx.y * 64, n0 = blockIdx.x * 64;
    int tid = threadIdx.x;
    int r = tid >> 2;            // 0..63
    int kq = (tid & 3) * 4;      // 0,4,8,12
    int tx = tid & 15, ty = tid >> 4;

    float acc[4][4];
    #pragma unroll
    for (int i = 0; i < 4; i++)
        #pragma unroll
        for (int j = 0; j < 4; j++) acc[i][j] = 0.f;

    for (int kt = 0; kt < K; kt += 16) {
        // A tile: rows m0..m0+63, k kt..kt+15 -> As[k][m]
        {
            int am = m0 + r;
            float4 av = make_float4(0.f, 0.f, 0.f, 0.f);
            if (am < M) av = *(const float4*)&A[(long long)am * lda + kt + kq];
            As[kq + 0][r] = av.x; As[kq + 1][r] = av.y;
            As[kq + 2][r] = av.z; As[kq + 3][r] = av.w;
        }
        if (TB) {
            int bn = n0 + r;
            float4 bv = make_float4(0.f, 0.f, 0.f, 0.f);
            if (bn < N) bv = *(const float4*)&Bm[(long long)bn * ldb + kt + kq];
            Bs[kq + 0][r] = bv.x; Bs[kq + 1][r] = bv.y;
            Bs[kq + 2][r] = bv.z; Bs[kq + 3][r] = bv.w;
        } else {
            int krow = tid >> 4;          // 0..15
            int nc = (tid & 15) * 4;      // 0..60
            int bn = n0 + nc;
            float4 bv = make_float4(0.f, 0.f, 0.f, 0.f);
            if (bn + 3 < N) bv = *(const float4*)&Bm[(long long)(kt + krow) * ldb + bn];
            *(float4*)&Bs[krow][nc] = bv;
        }
        __syncthreads();
        #pragma unroll
        for (int kk = 0; kk < 16; kk++) {
            float a[4], b[4];
            *(float4*)a = *(const float4*)&As[kk][ty * 4];
            *(float4*)b = *(const float4*)&Bs[kk][tx * 4];
            #pragma unroll
            for (int i = 0; i < 4; i++)
                #pragma unroll
                for (int j = 0; j < 4; j++) acc[i][j] = fmaf(a[i], b[j], acc[i][j]);
        }
        __syncthreads();
    }

    #pragma unroll
    for (int i = 0; i < 4; i++) {
        int m = m0 + ty * 4 + i;
        if (m >= M) continue;
        #pragma unroll
        for (int j = 0; j < 4; j++) {
            int n = n0 + tx * 4 + j;
            if (n >= N) continue;
            float v = acc[i][j];
            if (bias) v += bias[n];
            if (EPI == 1) v = 0.5f * v * (1.f + erff(v * 0.70710678118654752f));
            else if (EPI == 2) v = (v > 20.f) ? v : log1pf(__expf(v));
            if (resid) v += resid[(long long)m * ldc + n];
            C[(long long)m * ldc + n] = v;
        }
    }
}

// ---------------- softmax over scores rows (scale + mask fused) ----------------
__global__ void softmax_kernel(float* __restrict__ sc, const unsigned char* __restrict__ mask) {
    long long row = blockIdx.x;                 // b*H*L + h*L + l
    int b = (int)(row / ((long long)CH * CL));
    float* p = sc + row * (long long)CL;
    const unsigned char* mrow = mask + (long long)b * CL;
    const float scale = 0.125f;                 // 1/sqrt(64)

    float mx = -INFINITY;
    for (int s = threadIdx.x; s < CL; s += blockDim.x) {
        float v = mrow[s] ? -INFINITY : p[s] * scale;
        mx = fmaxf(mx, v);
    }
    mx = blockMax(mx);
    float sum = 0.f;
    for (int s = threadIdx.x; s < CL; s += blockDim.x) {
        float v = mrow[s] ? -INFINITY : p[s] * scale;
        float e = __expf(v - mx);
        p[s] = e;
        sum += e;
    }
    sum = blockSum(sum);
    float inv = 1.f / sum;
    for (int s = threadIdx.x; s < CL; s += blockDim.x) p[s] *= inv;
}

// ---------------- causal depthwise conv (KC=4) + SiLU ----------------
__global__ void conv_silu_kernel(const float* __restrict__ xz, const float* __restrict__ cw,
                                 const float* __restrict__ cb, float* __restrict__ uact) {
    long long idx = (long long)blockIdx.x * blockDim.x + threadIdx.x;
    if (idx >= (long long)CM * CDI) return;
    int di = (int)(idx % CDI);
    long long bl = idx / CDI;          // b*L + t
    int t = (int)(bl % CL);
    long long bbase = bl - t;          // b*L
    float acc = cb[di];
    #pragma unroll
    for (int kk = 0; kk < CKC; kk++) {
        int t2 = t + kk - (CKC - 1);
        if (t2 >= 0)
            acc = fmaf(xz[(bbase + t2) * (long long)(2 * CDI) + di], cw[di * CKC + kk], acc);
    }
    float sg = 1.f / (1.f + __expf(-acc));
    uact[idx] = acc * sg;
}

// ---------------- selective scan: one warp per (b,di) chain, 2 states/lane ----------------
// emits y = (sum_s h*C + u*D) * silu(z) directly
__global__ void scan_kernel(const float* __restrict__ delta, const float* __restrict__ uact,
                            const float* __restrict__ xdbc, const float* __restrict__ xz,
                            const float* __restrict__ A_log, const float* __restrict__ D_ssm,
                            float* __restrict__ y) {
    int wg = (int)(((long long)blockIdx.x * blockDim.x + threadIdx.x) >> 5);
    int lane = threadIdx.x & 31;
    if (wg >= CB * CDI) return;
    int b = wg >> 10;            // / CDI
    int di = wg & (CDI - 1);

    float a0 = -__expf(A_log[di * CS + lane]);
    float a1 = -__expf(A_log[di * CS + lane + 32]);
    float Dd = D_ssm[di];
    float h0 = 0.f, h1 = 0.f;

    const float* dptr = delta + (long long)b * CL * CDI + di;
    const float* uptr = uact + (long long)b * CL * CDI + di;
    const float* zptr = xz + (long long)b * CL * (2 * CDI) + CDI + di;
    const float* bc = xdbc + (long long)b * CL * (CR + 2 * CS);
    float* yptr = y + (long long)b * CL * CDI + di;

    for (int t = 0; t < CL; t++) {
        float dt = dptr[(long long)t * CDI];
        float uu = uptr[(long long)t * CDI];
        const float* xrow = bc + (long long)t * (CR + 2 * CS);
        float B0 = xrow[CR + lane];
        float B1 = xrow[CR + 32 + lane];
        float C0 = xrow[CR + CS + lane];
        float C1 = xrow[CR + CS + 32 + lane];
        float dA0 = __expf(dt * a0);
        float dA1 = __expf(dt * a1);
        float du = dt * uu;
        h0 = fmaf(h0, dA0, du * B0);
        h1 = fmaf(h1, dA1, du * B1);
        float acc = fmaf(h0, C0, h1 * C1);
        #pragma unroll
        for (int o = 16; o; o >>= 1) acc += __shfl_down_sync(0xffffffffu, acc, o);
        if (lane == 0) {
            float zv = zptr[(long long)t * (2 * CDI)];
            float sz = zv / (1.f + __expf(-zv));
            yptr[(long long)t * CDI] = (acc + uu * Dd) * sz;
        }
    }
}

// ---------------- residual add3 + LN1 + LN2 (both in one kernel) ----------------
__global__ void add_ln_kernel(const float* __restrict__ x, const float* __restrict__ attn,
                              const float* __restrict__ mamba,
                              const float* __restrict__ g1, const float* __restrict__ b1,
                              const float* __restrict__ g2, const float* __restrict__ b2,
                              float* __restrict__ hout, float* __restrict__ hnout) {
    long long row = blockIdx.x;
    const long long base = row * CD;
    float s[4];
    #pragma unroll
    for (int i = 0; i < 4; i++) {
        int c = threadIdx.x + i * 128;
        s[i] = x[base + c] + attn[base + c] + mamba[base + c];
    }
    float sum = s[0] + s[1] + s[2] + s[3];
    float mean = blockSum(sum) * (1.f / CD);
    float vs = 0.f;
    #pragma unroll
    for (int i = 0; i < 4; i++) { float d = s[i] - mean; vs += d * d; }
    float var = blockSum(vs) * (1.f / CD);
    float inv = rsqrtf(var + 1e-5f);
    float h[4];
    #pragma unroll
    for (int i = 0; i < 4; i++) {
        int c = threadIdx.x + i * 128;
        h[i] = (s[i] - mean) * inv * g1[c] + b1[c];
        hout[base + c] = h[i];
    }
    float sum2 = h[0] + h[1] + h[2] + h[3];
    float mean2 = blockSum(sum2) * (1.f / CD);
    float vs2 = 0.f;
    #pragma unroll
    for (int i = 0; i < 4; i++) { float d = h[i] - mean2; vs2 += d * d; }
    float var2 = blockSum(vs2) * (1.f / CD);
    float inv2 = rsqrtf(var2 + 1e-6f);
    #pragma unroll
    for (int i = 0; i < 4; i++) {
        int c = threadIdx.x + i * 128;
        hnout[base + c] = (h[i] - mean2) * inv2 * g2[c] + b2[c];
    }
}

// ---------------- host-side launch helpers ----------------
static void launch_gemm(int TB, int EPI,
                        const float* A, const float* B, const float* bias, const float* resid,
                        float* C, int M, int N, int K, int lda, int ldb, int ldc,
                        int batch = 1, int zdiv = 1,
                        long long sA1 = 0, long long sA2 = 0,
                        long long sB1 = 0, long long sB2 = 0,
                        long long sC1 = 0, long long sC2 = 0) {
    dim3 grid((N + 63) / 64, (M + 63) / 64, batch);
    dim3 block(256);
    if (TB == 1) {
        if (EPI == 0)
            sgemm_kernel<1, 0><<<grid, block>>>(A, B, bias, resid, C, M, N, K, lda, ldb, ldc,
                                                zdiv, sA1, sA2, sB1, sB2, sC1, sC2);
        else if (EPI == 1)
            sgemm_kernel<1, 1><<<grid, block>>>(A, B, bias, resid, C, M, N, K, lda, ldb, ldc,
                                                zdiv, sA1, sA2, sB1, sB2, sC1, sC2);
        else
            sgemm_kernel<1, 2><<<grid, block>>>(A, B, bias, resid, C, M, N, K, lda, ldb, ldc,
                                                zdiv, sA1, sA2, sB1, sB2, sC1, sC2);
    } else {
        sgemm_kernel<0, 0><<<grid, block>>>(A, B, bias, resid, C, M, N, K, lda, ldb, ldc,
                                            zdiv, sA1, sA2, sB1, sB2, sC1, sC2);
    }
}

extern "C" void kernel_launch(void* const* d_in, const int* in_sizes, int n_in,
                              void* d_out, int out_size) {
    const float* x          = (const float*)d_in[0];
    const unsigned char* mask = (const unsigned char*)d_in[1];
    const float* Wq = (const float*)d_in[2];
    const float* bq = (const float*)d_in[3];
    const float* Wk = (const float*)d_in[4];
    const float* bk = (const float*)d_in[5];
    const float* Wv = (const float*)d_in[6];
    const float* bv = (const float*)d_in[7];
    const float* Wo = (const float*)d_in[8];
    const float* bo = (const float*)d_in[9];
    const float* in_proj_w = (const float*)d_in[10];
    const float* conv_w    = (const float*)d_in[11];
    const float* conv_b    = (const float*)d_in[12];
    const float* x_proj_w  = (const float*)d_in[13];
    const float* dt_proj_w = (const float*)d_in[14];
    const float* dt_proj_b = (const float*)d_in[15];
    const float* A_log     = (const float*)d_in[16];
    const float* D_ssm     = (const float*)d_in[17];
    const float* out_proj_w = (const float*)d_in[18];
    const float* ln1_g = (const float*)d_in[19];
    const float* ln1_b = (const float*)d_in[20];
    const float* ffn_w1 = (const float*)d_in[21];
    const float* ffn_b1 = (const float*)d_in[22];
    const float* ffn_w2 = (const float*)d_in[23];
    const float* ffn_b2 = (const float*)d_in[24];
    const float* ln2_g = (const float*)d_in[25];
    const float* ln2_b = (const float*)d_in[26];
    float* out = (float*)d_out;

    float *q, *k, *v, *scores, *attn, *xattn, *xz, *uact, *xdbc, *delta, *yss, *mamba, *h, *hn, *ff1;
    cudaGetSymbolAddress((void**)&q, g_q);
    cudaGetSymbolAddress((void**)&k, g_k);
    cudaGetSymbolAddress((void**)&v, g_v);
    cudaGetSymbolAddress((void**)&scores, g_scores);
    cudaGetSymbolAddress((void**)&attn, g_attn);
    cudaGetSymbolAddress((void**)&xattn, g_xattn);
    cudaGetSymbolAddress((void**)&xz, g_xz);
    cudaGetSymbolAddress((void**)&uact, g_uact);
    cudaGetSymbolAddress((void**)&xdbc, g_xdbc);
    cudaGetSymbolAddress((void**)&delta, g_delta);
    cudaGetSymbolAddress((void**)&yss, g_yss);
    cudaGetSymbolAddress((void**)&mamba, g_mamba);
    cudaGetSymbolAddress((void**)&h, g_h);
    cudaGetSymbolAddress((void**)&hn, g_hn);
    cudaGetSymbolAddress((void**)&ff1, g_ff1);

    // ---- attention ----
    launch_gemm(1, 0, x, Wq, bq, nullptr, q, CM, CD, CD, CD, CD, CD);
    launch_gemm(1, 0, x, Wk, bk, nullptr, k, CM, CD, CD, CD, CD, CD);
    launch_gemm(1, 0, x, Wv, bv, nullptr, v, CM, CD, CD, CD, CD, CD);

    // scores[b,h,l,s] = q[b,l,h,:] . k[b,s,h,:]   (batched over z = b*H+h)
    launch_gemm(1, 0, q, k, nullptr, nullptr, scores, CL, CL, CE, CD, CD, CL,
                CB * CH, CH,
                (long long)CL * CD, CE,
                (long long)CL * CD, CE,
                (long long)CH * CL * CL, (long long)CL * CL);

    softmax_kernel<<<CB * CH * CL, 128>>>(scores, mask);

    // attn[b,l,h,:] = sum_s probs[b,h,l,s] * v[b,s,h,:]   (NN batched)
    launch_gemm(0, 0, scores, v, nullptr, nullptr, attn, CL, CE, CL, CL, CD, CD,
                CB * CH, CH,
                (long long)CH * CL * CL, (long long)CL * CL,
                (long long)CL * CD, CE,
                (long long)CL * CD, CE);

    launch_gemm(1, 0, attn, Wo, bo, nullptr, xattn, CM, CD, CD, CD, CD, CD);

    // ---- mamba ----
    launch_gemm(1, 0, x, in_proj_w, nullptr, nullptr, xz, CM, 2 * CDI, CD, CD, CD, 2 * CDI);

    {
        long long n = (long long)CM * CDI;
        conv_silu_kernel<<<(unsigned)((n + 255) / 256), 256>>>(xz, conv_w, conv_b, uact);
    }

    launch_gemm(1, 0, uact, x_proj_w, nullptr, nullptr, xdbc, CM, CR + 2 * CS, CDI,
                CDI, CDI, CR + 2 * CS);

    launch_gemm(1, 2, xdbc, dt_proj_w, dt_proj_b, nullptr, delta, CM, CDI, CR,
                CR + 2 * CS, CR, CDI);

    scan_kernel<<<(CB * CDI * 32) / 256, 256>>>(delta, uact, xdbc, xz, A_log, D_ssm, yss);

    launch_gemm(1, 0, yss, out_proj_w, nullptr, nullptr, mamba, CM, CD, CDI, CDI, CDI, CD);

    // ---- residual + LN1 + LN2 ----
    add_ln_kernel<<<CM, 128>>>(x, xattn, mamba, ln1_g, ln1_b, ln2_g, ln2_b, h, hn);

    // ---- FFN (GELU epilogue; residual fused into second GEMM) ----
    launch_gemm(1, 1, hn, ffn_w1, ffn_b1, nullptr, ff1, CM, CDFF, CD, CD, CD, CDFF);
    launch_gemm(1, 0, ff1, ffn_w2, ffn_b2, h, out, CM, CD, CDFF, CDFF, CDFF, CD);
}

// round 3
// speedup vs baseline: 1.8718x; 1.8718x over previous
#include <cuda_runtime.h>
#include <math.h>

// ---------------- problem constants ----------------
#define CB   8
#define CT   24
#define CW   48
#define CD   512
#define CH   8
#define CE   64
#define CDI  1024
#define CS   64
#define CR   32
#define CKC  4
#define CDFF 2048
#define CL   1152          // T*W
#define CM   9216          // B*L

// ---------------- scratch (device globals; no cudaMalloc allowed) ----------------
__device__ float g_q[CM * CD];
__device__ float g_k[CM * CD];
__device__ float g_v[CM * CD];
__device__ float g_scores[(size_t)CB * CH * CL * CL];   // 340 MB, reused as probs
__device__ float g_attn[CM * CD];
__device__ float g_xattn[CM * CD];
__device__ float g_xz[CM * 2 * CDI];
__device__ float g_uact[CM * CDI];
__device__ float g_xdbc[CM * (CR + 2 * CS)];
__device__ float g_delta[CM * CDI];
__device__ float g_yss[CM * CDI];
__device__ float g_mamba[CM * CD];
__device__ float g_h[CM * CD];
__device__ float g_hn[CM * CD];
__device__ float g_ff1[CM * CDFF];

// ---------------- reductions ----------------
__device__ __forceinline__ float warpSum(float v) {
    #pragma unroll
    for (int o = 16; o; o >>= 1) v += __shfl_xor_sync(0xffffffffu, v, o);
    return v;
}
__device__ __forceinline__ float warpMax(float v) {
    #pragma unroll
    for (int o = 16; o; o >>= 1) v = fmaxf(v, __shfl_xor_sync(0xffffffffu, v, o));
    return v;
}
__device__ float blockSum(float v) {
    __shared__ float sh[32];
    int lane = threadIdx.x & 31, wid = threadIdx.x >> 5;
    v = warpSum(v);
    if (lane == 0) sh[wid] = v;
    __syncthreads();
    int nw = blockDim.x >> 5;
    v = (threadIdx.x < nw) ? sh[threadIdx.x] : 0.f;
    if (wid == 0) v = warpSum(v);
    if (threadIdx.x == 0) sh[0] = v;
    __syncthreads();
    float r = sh[0];
    __syncthreads();
    return r;
}
__device__ float blockMax(float v) {
    __shared__ float sh[32];
    int lane = threadIdx.x & 31, wid = threadIdx.x >> 5;
    v = warpMax(v);
    if (lane == 0) sh[wid] = v;
    __syncthreads();
    int nw = blockDim.x >> 5;
    v = (threadIdx.x < nw) ? sh[threadIdx.x] : -INFINITY;
    if (wid == 0) v = warpMax(v);
    if (threadIdx.x == 0) sh[0] = v;
    __syncthreads();
    float r = sh[0];
    __syncthreads();
    return r;
}

// ---------------- tf32 helpers ----------------
__device__ __forceinline__ unsigned f2tf(float f) {
    unsigned u;
    asm("cvt.rna.tf32.f32 %0, %1;" : "=r"(u) : "f"(f));
    return u;
}
__device__ __forceinline__ void mma8(float* c, const unsigned* a, const unsigned* b) {
    asm volatile("mma.sync.aligned.m16n8k8.row.col.f32.tf32.tf32.f32 "
                 "{%0,%1,%2,%3}, {%4,%5,%6,%7}, {%8,%9}, {%0,%1,%2,%3};\n"
                 : "+f"(c[0]), "+f"(c[1]), "+f"(c[2]), "+f"(c[3])
                 : "r"(a[0]), "r"(a[1]), "r"(a[2]), "r"(a[3]),
                   "r"(b[0]), "r"(b[1]));
}

// ---------------- tf32 tensor-core GEMM ----------------
// TB=1: C[m,n] = sum_k A[m,k]*B[n,k]   (torch Linear: both K-contiguous)
// TB=0: C[m,n] = sum_k A[m,k]*B[k,n]   (NN, for probs @ V)
// Tile: 128 x BN (BN in {128, 64}), BK=16, 256 threads (8 warps).
// Requirements: M % 128 == 0, K % 16 == 0 (true for all call sites).
// EPI: 0 none, 1 exact GELU, 2 softplus.  Batched via blockIdx.z.
template <int TB, int EPI, int BN>
__global__ __launch_bounds__(256, 2)
void tgemm_kernel(const float* __restrict__ A, const float* __restrict__ Bm,
                  const float* __restrict__ bias, const float* __restrict__ resid,
                  float* __restrict__ C,
                  int M, int N, int K, int lda, int ldb, int ldc,
                  int zdiv, long long sA1, long long sA2,
                  long long sB1, long long sB2,
                  long long sC1, long long sC2) {
    constexpr int NI = BN / 16;        // mma n-tiles per warp
    constexpr int NBI = BN / 64;       // B-tile load iterations
    __shared__ unsigned As[16][136];
    __shared__ unsigned Bs[16][136];

    int z = blockIdx.z;
    int zq = z / zdiv, zr = z - zq * zdiv;
    A += zq * sA1 + (long long)zr * sA2;
    Bm += zq * sB1 + (long long)zr * sB2;
    C += zq * sC1 + (long long)zr * sC2;
    const float* Rp = resid ? (resid + zq * sC1 + (long long)zr * sC2) : nullptr;

    const int m0 = blockIdx.y * 128, n0 = blockIdx.x * BN;
    const int tid = threadIdx.x;
    const int lane = tid & 31, warp = tid >> 5;
    const int grp = lane >> 2, tig = lane & 3;
    const int wm0 = (warp & 3) * 32;
    const int wn0 = (warp >> 2) * (BN / 2);

    // A / B(TB=1) g->s loader indices: row = ar(+64), k-quad = akq..akq+3
    const int ar = tid >> 2;                 // 0..63
    const int akq = (tid & 3) * 4;           // 0,4,8,12
    const int aqx = (akq >> 2) << 3;         // swizzle xor for this k-quad

    // B(TB=0) loader indices
    const int bkr = (BN == 128) ? (tid >> 5) : (tid >> 4);
    const int bnq = (BN == 128) ? ((tid & 31) * 4) : ((tid & 15) * 4);

    float c[2][NI][4];
    #pragma unroll
    for (int mi = 0; mi < 2; mi++)
        #pragma unroll
        for (int ni = 0; ni < NI; ni++)
            #pragma unroll
            for (int j = 0; j < 4; j++) c[mi][ni][j] = 0.f;

    float4 aR[2], bR[2];
    const float4 z4 = make_float4(0.f, 0.f, 0.f, 0.f);

    auto loadTiles = [&](int kt) {
        #pragma unroll
        for (int i = 0; i < 2; i++)
            aR[i] = *(const float4*)&A[(long long)(m0 + ar + i * 64) * lda + kt + akq];
        #pragma unroll
        for (int i = 0; i < NBI; i++) {
            if (TB) {
                int bn = n0 + ar + i * 64;
                bR[i] = (bn < N) ? *(const float4*)&Bm[(long long)bn * ldb + kt + akq] : z4;
            } else {
                int nn = n0 + bnq;
                int kk = kt + bkr + i * 8;
                bR[i] = (nn < N) ? *(const float4*)&Bm[(long long)kk * ldb + nn] : z4;
            }
        }
    };
    auto storeTiles = [&]() {
        #pragma unroll
        for (int i = 0; i < 2; i++) {
            int m = (ar + i * 64) ^ aqx;
            As[akq + 0][m] = f2tf(aR[i].x);
            As[akq + 1][m] = f2tf(aR[i].y);
            As[akq + 2][m] = f2tf(aR[i].z);
            As[akq + 3][m] = f2tf(aR[i].w);
        }
        #pragma unroll
        for (int i = 0; i < NBI; i++) {
            if (TB) {
                int n = (ar + i * 64) ^ aqx;
                Bs[akq + 0][n] = f2tf(bR[i].x);
                Bs[akq + 1][n] = f2tf(bR[i].y);
                Bs[akq + 2][n] = f2tf(bR[i].z);
                Bs[akq + 3][n] = f2tf(bR[i].w);
            } else {
                int kk = bkr + i * 8;
                int qx = ((kk >> 2) & 3) << 3;
                uint4 u;
                u.x = f2tf(bR[i].x); u.y = f2tf(bR[i].y);
                u.z = f2tf(bR[i].z); u.w = f2tf(bR[i].w);
                *(uint4*)&Bs[kk][bnq ^ qx] = u;
            }
        }
    };

    loadTiles(0);
    storeTiles();
    __syncthreads();

    for (int kt = 0; kt < K; kt += 16) {
        bool more = (kt + 16) < K;
        if (more) loadTiles(kt + 16);

        #pragma unroll
        for (int ks = 0; ks < 16; ks += 8) {
            const int xlo = (ks >> 2) << 3;   // 0 or 16
            const int xhi = xlo + 8;
            unsigned af[2][4];
            #pragma unroll
            for (int mi = 0; mi < 2; mi++) {
                int m = wm0 + mi * 16 + grp;
                af[mi][0] = As[ks + tig][m ^ xlo];
                af[mi][1] = As[ks + tig][(m + 8) ^ xlo];
                af[mi][2] = As[ks + tig + 4][m ^ xhi];
                af[mi][3] = As[ks + tig + 4][(m + 8) ^ xhi];
            }
            unsigned bf[NI][2];
            #pragma unroll
            for (int ni = 0; ni < NI; ni++) {
                int n = wn0 + ni * 8 + grp;
                bf[ni][0] = Bs[ks + tig][n ^ xlo];
                bf[ni][1] = Bs[ks + tig + 4][n ^ xhi];
            }
            #pragma unroll
            for (int mi = 0; mi < 2; mi++)
                #pragma unroll
                for (int ni = 0; ni < NI; ni++)
                    mma8(c[mi][ni], af[mi], bf[ni]);
        }
        __syncthreads();
        if (more) {
            storeTiles();
            __syncthreads();
        }
    }

    // ---- epilogue ----
    #pragma unroll
    for (int mi = 0; mi < 2; mi++) {
        int r0 = m0 + wm0 + mi * 16 + grp;
        #pragma unroll
        for (int ni = 0; ni < NI; ni++) {
            int col = n0 + wn0 + ni * 8 + 2 * tig;
            if (col >= N) continue;
            float bx = 0.f, by = 0.f;
            if (bias) { bx = bias[col]; by = bias[col + 1]; }
            float v0 = c[mi][ni][0] + bx, v1 = c[mi][ni][1] + by;
            float v2 = c[mi][ni][2] + bx, v3 = c[mi][ni][3] + by;
            if (EPI == 1) {
                v0 = 0.5f * v0 * (1.f + erff(v0 * 0.70710678118654752f));
                v1 = 0.5f * v1 * (1.f + erff(v1 * 0.70710678118654752f));
                v2 = 0.5f * v2 * (1.f + erff(v2 * 0.70710678118654752f));
                v3 = 0.5f * v3 * (1.f + erff(v3 * 0.70710678118654752f));
            } else if (EPI == 2) {
                v0 = (v0 > 20.f) ? v0 : log1pf(__expf(v0));
                v1 = (v1 > 20.f) ? v1 : log1pf(__expf(v1));
                v2 = (v2 > 20.f) ? v2 : log1pf(__expf(v2));
                v3 = (v3 > 20.f) ? v3 : log1pf(__expf(v3));
            }
            if (Rp) {
                float2 ra = *(const float2*)&Rp[(long long)r0 * ldc + col];
                float2 rb = *(const float2*)&Rp[(long long)(r0 + 8) * ldc + col];
                v0 += ra.x; v1 += ra.y; v2 += rb.x; v3 += rb.y;
            }
            *(float2*)&C[(long long)r0 * ldc + col] = make_float2(v0, v1);
            *(float2*)&C[(long long)(r0 + 8) * ldc + col] = make_float2(v2, v3);
        }
    }
}

// ---------------- softmax over scores rows (scale + mask fused) ----------------
__global__ void softmax_kernel(float* __restrict__ sc, const unsigned char* __restrict__ mask) {
    long long row = blockIdx.x;                 // b*H*L + h*L + l
    int b = (int)(row / ((long long)CH * CL));
    float* p = sc + row * (long long)CL;
    const unsigned char* mrow = mask + (long long)b * CL;
    const float scale = 0.125f;                 // 1/sqrt(64)

    float mx = -INFINITY;
    for (int s = threadIdx.x; s < CL; s += blockDim.x) {
        float v = mrow[s] ? -INFINITY : p[s] * scale;
        mx = fmaxf(mx, v);
    }
    mx = blockMax(mx);
    float sum = 0.f;
    for (int s = threadIdx.x; s < CL; s += blockDim.x) {
        float v = mrow[s] ? -INFINITY : p[s] * scale;
        float e = __expf(v - mx);
        p[s] = e;
        sum += e;
    }
    sum = blockSum(sum);
    float inv = 1.f / sum;
    for (int s = threadIdx.x; s < CL; s += blockDim.x) p[s] *= inv;
}

// ---------------- causal depthwise conv (KC=4) + SiLU ----------------
__global__ void conv_silu_kernel(const float* __restrict__ xz, const float* __restrict__ cw,
                                 const float* __restrict__ cb, float* __restrict__ uact) {
    long long idx = (long long)blockIdx.x * blockDim.x + threadIdx.x;
    if (idx >= (long long)CM * CDI) return;
    int di = (int)(idx % CDI);
    long long bl = idx / CDI;          // b*L + t
    int t = (int)(bl % CL);
    long long bbase = bl - t;          // b*L
    float acc = cb[di];
    #pragma unroll
    for (int kk = 0; kk < CKC; kk++) {
        int t2 = t + kk - (CKC - 1);
        if (t2 >= 0)
            acc = fmaf(xz[(bbase + t2) * (long long)(2 * CDI) + di], cw[di * CKC + kk], acc);
    }
    float sg = 1.f / (1.f + __expf(-acc));
    uact[idx] = acc * sg;
}

// ---------------- selective scan: one warp per (b,di) chain, 2 states/lane ----------------
__global__ void scan_kernel(const float* __restrict__ delta, const float* __restrict__ uact,
                            const float* __restrict__ xdbc, const float* __restrict__ xz,
                            const float* __restrict__ A_log, const float* __restrict__ D_ssm,
                            float* __restrict__ y) {
    int wg = (int)(((long long)blockIdx.x * blockDim.x + threadIdx.x) >> 5);
    int lane = threadIdx.x & 31;
    if (wg >= CB * CDI) return;
    int b = wg >> 10;            // / CDI
    int di = wg & (CDI - 1);

    float a0 = -__expf(A_log[di * CS + lane]);
    float a1 = -__expf(A_log[di * CS + lane + 32]);
    float Dd = D_ssm[di];
    float h0 = 0.f, h1 = 0.f;

    const float* dptr = delta + (long long)b * CL * CDI + di;
    const float* uptr = uact + (long long)b * CL * CDI + di;
    const float* zptr = xz + (long long)b * CL * (2 * CDI) + CDI + di;
    const float* bc = xdbc + (long long)b * CL * (CR + 2 * CS);
    float* yptr = y + (long long)b * CL * CDI + di;

    for (int t = 0; t < CL; t++) {
        float dt = dptr[(long long)t * CDI];
        float uu = uptr[(long long)t * CDI];
        const float* xrow = bc + (long long)t * (CR + 2 * CS);
        float B0 = xrow[CR + lane];
        float B1 = xrow[CR + 32 + lane];
        float C0 = xrow[CR + CS + lane];
        float C1 = xrow[CR + CS + 32 + lane];
        float dA0 = __expf(dt * a0);
        float dA1 = __expf(dt * a1);
        float du = dt * uu;
        h0 = fmaf(h0, dA0, du * B0);
        h1 = fmaf(h1, dA1, du * B1);
        float acc = fmaf(h0, C0, h1 * C1);
        #pragma unroll
        for (int o = 16; o; o >>= 1) acc += __shfl_down_sync(0xffffffffu, acc, o);
        if (lane == 0) {
            float zv = zptr[(long long)t * (2 * CDI)];
            float sz = zv / (1.f + __expf(-zv));
            yptr[(long long)t * CDI] = (acc + uu * Dd) * sz;
        }
    }
}

// ---------------- residual add3 + LN1 + LN2 (both in one kernel) ----------------
__global__ void add_ln_kernel(const float* __restrict__ x, const float* __restrict__ attn,
                              const float* __restrict__ mamba,
                              const float* __restrict__ g1, const float* __restrict__ b1,
                              const float* __restrict__ g2, const float* __restrict__ b2,
                              float* __restrict__ hout, float* __restrict__ hnout) {
    long long row = blockIdx.x;
    const long long base = row * CD;
    float s[4];
    #pragma unroll
    for (int i = 0; i < 4; i++) {
        int c = threadIdx.x + i * 128;
        s[i] = x[base + c] + attn[base + c] + mamba[base + c];
    }
    float sum = s[0] + s[1] + s[2] + s[3];
    float mean = blockSum(sum) * (1.f / CD);
    float vs = 0.f;
    #pragma unroll
    for (int i = 0; i < 4; i++) { float d = s[i] - mean; vs += d * d; }
    float var = blockSum(vs) * (1.f / CD);
    float inv = rsqrtf(var + 1e-5f);
    float h[4];
    #pragma unroll
    for (int i = 0; i < 4; i++) {
        int c = threadIdx.x + i * 128;
        h[i] = (s[i] - mean) * inv * g1[c] + b1[c];
        hout[base + c] = h[i];
    }
    float sum2 = h[0] + h[1] + h[2] + h[3];
    float mean2 = blockSum(sum2) * (1.f / CD);
    float vs2 = 0.f;
    #pragma unroll
    for (int i = 0; i < 4; i++) { float d = h[i] - mean2; vs2 += d * d; }
    float var2 = blockSum(vs2) * (1.f / CD);
    float inv2 = rsqrtf(var2 + 1e-6f);
    #pragma unroll
    for (int i = 0; i < 4; i++) {
        int c = threadIdx.x + i * 128;
        hnout[base + c] = (h[i] - mean2) * inv2 * g2[c] + b2[c];
    }
}

// ---------------- host ----------------
static inline dim3 tg_grid(int M, int N, int BN, int batch) {
    return dim3((N + BN - 1) / BN, (M + 127) / 128, batch);
}

extern "C" void kernel_launch(void* const* d_in, const int* in_sizes, int n_in,
                              void* d_out, int out_size) {
    const float* x          = (const float*)d_in[0];
    const unsigned char* mask = (const unsigned char*)d_in[1];
    const float* Wq = (const float*)d_in[2];
    const float* bq = (const float*)d_in[3];
    const float* Wk = (const float*)d_in[4];
    const float* bk = (const float*)d_in[5];
    const float* Wv = (const float*)d_in[6];
    const float* bv = (const float*)d_in[7];
    const float* Wo = (const float*)d_in[8];
    const float* bo = (const float*)d_in[9];
    const float* in_proj_w = (const float*)d_in[10];
    const float* conv_w    = (const float*)d_in[11];
    const float* conv_b    = (const float*)d_in[12];
    const float* x_proj_w  = (const float*)d_in[13];
    const float* dt_proj_w = (const float*)d_in[14];
    const float* dt_proj_b = (const float*)d_in[15];
    const float* A_log     = (const float*)d_in[16];
    const float* D_ssm     = (const float*)d_in[17];
    const float* out_proj_w = (const float*)d_in[18];
    const float* ln1_g = (const float*)d_in[19];
    const float* ln1_b = (const float*)d_in[20];
    const float* ffn_w1 = (const float*)d_in[21];
    const float* ffn_b1 = (const float*)d_in[22];
    const float* ffn_w2 = (const float*)d_in[23];
    const float* ffn_b2 = (const float*)d_in[24];
    const float* ln2_g = (const float*)d_in[25];
    const float* ln2_b = (const float*)d_in[26];
    float* out = (float*)d_out;

    float *q, *k, *v, *scores, *attn, *xattn, *xz, *uact, *xdbc, *delta, *yss, *mamba, *h, *hn, *ff1;
    cudaGetSymbolAddress((void**)&q, g_q);
    cudaGetSymbolAddress((void**)&k, g_k);
    cudaGetSymbolAddress((void**)&v, g_v);
    cudaGetSymbolAddress((void**)&scores, g_scores);
    cudaGetSymbolAddress((void**)&attn, g_attn);
    cudaGetSymbolAddress((void**)&xattn, g_xattn);
    cudaGetSymbolAddress((void**)&xz, g_xz);
    cudaGetSymbolAddress((void**)&uact, g_uact);
    cudaGetSymbolAddress((void**)&xdbc, g_xdbc);
    cudaGetSymbolAddress((void**)&delta, g_delta);
    cudaGetSymbolAddress((void**)&yss, g_yss);
    cudaGetSymbolAddress((void**)&mamba, g_mamba);
    cudaGetSymbolAddress((void**)&h, g_h);
    cudaGetSymbolAddress((void**)&hn, g_hn);
    cudaGetSymbolAddress((void**)&ff1, g_ff1);

    // ---- attention ----
    tgemm_kernel<1, 0, 128><<<tg_grid(CM, CD, 128, 1), 256>>>(
        x, Wq, bq, nullptr, q, CM, CD, CD, CD, CD, CD, 1, 0, 0, 0, 0, 0, 0);
    tgemm_kernel<1, 0, 128><<<tg_grid(CM, CD, 128, 1), 256>>>(
        x, Wk, bk, nullptr, k, CM, CD, CD, CD, CD, CD, 1, 0, 0, 0, 0, 0, 0);
    tgemm_kernel<1, 0, 128><<<tg_grid(CM, CD, 128, 1), 256>>>(
        x, Wv, bv, nullptr, v, CM, CD, CD, CD, CD, CD, 1, 0, 0, 0, 0, 0, 0);

    // scores[b,h,l,s] = q[b,l,h,:] . k[b,s,h,:]   (batched over z = b*H+h)
    tgemm_kernel<1, 0, 128><<<tg_grid(CL, CL, 128, CB * CH), 256>>>(
        q, k, nullptr, nullptr, scores, CL, CL, CE, CD, CD, CL,
        CH,
        (long long)CL * CD, CE,
        (long long)CL * CD, CE,
        (long long)CH * CL * CL, (long long)CL * CL);

    softmax_kernel<<<CB * CH * CL, 128>>>(scores, mask);

    // attn[b,l,h,:] = sum_s probs[b,h,l,s] * v[b,s,h,:]   (NN batched, BN=64)
    tgemm_kernel<0, 0, 64><<<tg_grid(CL, CE, 64, CB * CH), 256>>>(
        scores, v, nullptr, nullptr, attn, CL, CE, CL, CL, CD, CD,
        CH,
        (long long)CH * CL * CL, (long long)CL * CL,
        (long long)CL * CD, CE,
        (long long)CL * CD, CE);

    tgemm_kernel<1, 0, 128><<<tg_grid(CM, CD, 128, 1), 256>>>(
        attn, Wo, bo, nullptr, xattn, CM, CD, CD, CD, CD, CD, 1, 0, 0, 0, 0, 0, 0);

    // ---- mamba ----
    tgemm_kernel<1, 0, 128><<<tg_grid(CM, 2 * CDI, 128, 1), 256>>>(
        x, in_proj_w, nullptr, nullptr, xz, CM, 2 * CDI, CD, CD, CD, 2 * CDI,
        1, 0, 0, 0, 0, 0, 0);

    {
        long long n = (long long)CM * CDI;
        conv_silu_kernel<<<(unsigned)((n + 255) / 256), 256>>>(xz, conv_w, conv_b, uact);
    }

    tgemm_kernel<1, 0, 128><<<tg_grid(CM, CR + 2 * CS, 128, 1), 256>>>(
        uact, x_proj_w, nullptr, nullptr, xdbc, CM, CR + 2 * CS, CDI,
        CDI, CDI, CR + 2 * CS, 1, 0, 0, 0, 0, 0, 0);

    tgemm_kernel<1, 2, 128><<<tg_grid(CM, CDI, 128, 1), 256>>>(
        xdbc, dt_proj_w, dt_proj_b, nullptr, delta, CM, CDI, CR,
        CR + 2 * CS, CR, CDI, 1, 0, 0, 0, 0, 0, 0);

    scan_kernel<<<(CB * CDI * 32) / 256, 256>>>(delta, uact, xdbc, xz, A_log, D_ssm, yss);

    tgemm_kernel<1, 0, 128><<<tg_grid(CM, CD, 128, 1), 256>>>(
        yss, out_proj_w, nullptr, nullptr, mamba, CM, CD, CDI, CDI, CDI, CD,
        1, 0, 0, 0, 0, 0, 0);

    // ---- residual + LN1 + LN2 ----
    add_ln_kernel<<<CM, 128>>>(x, xattn, mamba, ln1_g, ln1_b, ln2_g, ln2_b, h, hn);

    // ---- FFN (GELU epilogue; residual fused into second GEMM) ----
    tgemm_kernel<1, 1, 128><<<tg_grid(CM, CDFF, 128, 1), 256>>>(
        hn, ffn_w1, ffn_b1, nullptr, ff1, CM, CDFF, CD, CD, CD, CDFF,
        1, 0, 0, 0, 0, 0, 0);
    tgemm_kernel<1, 0, 128><<<tg_grid(CM, CD, 128, 1), 256>>>(
        ff1, ffn_w2, ffn_b2, h, out, CM, CD, CDFF, CDFF, CDFF, CD,
        1, 0, 0, 0, 0, 0, 0);
}